// round 4
// baseline (speedup 1.0000x reference)
#include <cuda_runtime.h>
#include <math.h>

// Problem dims
#define BATCH 8192
#define OBS 64
#define ACT 16
#define HID 128
#define CON 256
#define COMP 85
#define KS 32

// ---------------- scratch (device globals; no allocation) ----------------
__device__ float g_G[COMP * COMP];          // W1 W1^T
__device__ float g_fout[BATCH * COMP];      // f-net output (relu(p3))
__device__ float g_kout[BATCH];             // k-net output (softplus)
__device__ unsigned g_d1m[BATCH * 3];       // d1 bitmask (85 bits in 3 words)
__device__ unsigned g_d2m[BATCH * 3];       // d2 bitmask

// =========================================================================
// Kernel 1: G = mw1 @ mw1^T   (85x85, K=256). One warp per output element.
// =========================================================================
__global__ __launch_bounds__(256)
void g_kernel(const float* __restrict__ mw1) {
    int gw = (blockIdx.x * 256 + threadIdx.x) >> 5;   // global warp id
    int lane = threadIdx.x & 31;
    if (gw >= COMP * COMP) return;
    int i = gw / COMP;
    int j = gw - i * COMP;
    const float4* a = (const float4*)(mw1 + i * CON);
    const float4* b = (const float4*)(mw1 + j * CON);
    float acc = 0.f;
    #pragma unroll
    for (int t = 0; t < 2; t++) {
        float4 av = a[lane + 32 * t];
        float4 bv = b[lane + 32 * t];
        acc += av.x * bv.x + av.y * bv.y + av.z * bv.z + av.w * bv.w;
    }
    #pragma unroll
    for (int off = 16; off; off >>= 1)
        acc += __shfl_down_sync(0xFFFFFFFFu, acc, off);
    if (lane == 0) g_G[gw] = acc;
}

// =========================================================================
// Kernel 2: fused forward pass. 64 samples per CTA, 512 threads.
// =========================================================================
#define TS 64
#define FWD_THREADS 512

// smem layout (float offsets)
#define O_X   0            // x buffer 64 x 257 (concat of/af)
#define XS    257
#define O_W   16448        // weight staging 16512 floats
#define O_T   32960        // head layer-1 temp 64 x 129
#define TBS   129
#define O_IN  41216        // input staging 64 x 65 (also k1/k2 bufs)
#define O_K1  41216        // k1: 64 x 33
#define O_K2  43328        // k2: 64 x 17
#define O_H1  45376        // h1 / f_out: 64 x 87
#define O_H2  50944        // h2: 64 x 87
#define HS    87
#define FWD_SMEM_FLOATS 56512
#define FWD_SMEM_BYTES  (FWD_SMEM_FLOATS * 4)

#define ACT_RELU 0
#define ACT_TANH 1

template<int N, int ACTT>
__device__ __forceinline__ void layer_fwd(
    float* __restrict__ sm,
    int o_out, int outStride, int outColOff,
    int o_in, int inStride,
    const float* __restrict__ Wg, const float* __restrict__ bg, int K)
{
    constexpr int NJ = (N + 31) / 32;
    const int tid = threadIdx.x;
    const int sp = tid >> 5;       // 0..15, samples 4sp..4sp+3
    const int q = tid & 31;        // output col group

    float acc[4][NJ];
    #pragma unroll
    for (int s = 0; s < 4; s++)
        #pragma unroll
        for (int j = 0; j < NJ; j++) acc[s][j] = 0.f;

    float* wbuf = sm + O_W;

    for (int k0 = 0; k0 < K; k0 += 128) {
        int KC = K - k0; if (KC > 128) KC = 128;
        int WS = KC | 1;   // odd stride -> conflict-free weight columns
        __syncthreads();
        for (int i = tid; i < N * KC; i += FWD_THREADS) {
            int r = i / KC;
            int c = i - r * KC;
            wbuf[r * WS + c] = Wg[r * K + k0 + c];
        }
        __syncthreads();
        const float* in0 = sm + o_in + (4 * sp + 0) * inStride + k0;
        const float* in1 = sm + o_in + (4 * sp + 1) * inStride + k0;
        const float* in2 = sm + o_in + (4 * sp + 2) * inStride + k0;
        const float* in3 = sm + o_in + (4 * sp + 3) * inStride + k0;
        #pragma unroll 2
        for (int k = 0; k < KC; k++) {
            float a0 = in0[k], a1 = in1[k], a2 = in2[k], a3 = in3[k];
            const float* wr = wbuf + k + q * WS;
            #pragma unroll
            for (int j = 0; j < NJ; j++) {
                float w = wr[(j << 5) * WS];
                acc[0][j] = fmaf(a0, w, acc[0][j]);
                acc[1][j] = fmaf(a1, w, acc[1][j]);
                acc[2][j] = fmaf(a2, w, acc[2][j]);
                acc[3][j] = fmaf(a3, w, acc[3][j]);
            }
        }
    }
    #pragma unroll
    for (int j = 0; j < NJ; j++) {
        int o = q + (j << 5);
        if (o < N) {
            float bv = bg[o];
            #pragma unroll
            for (int s = 0; s < 4; s++) {
                float v = acc[s][j] + bv;
                if (ACTT == ACT_RELU) v = fmaxf(v, 0.f);
                else if (ACTT == ACT_TANH) v = tanhf(v);
                sm[o_out + (4 * sp + s) * outStride + outColOff + o] = v;
            }
        }
    }
    __syncthreads();
}

__global__ __launch_bounds__(FWD_THREADS)
void fwd_kernel(
    const float* __restrict__ obs, const float* __restrict__ action,
    const float* __restrict__ ow1, const float* __restrict__ ob1,
    const float* __restrict__ ow2, const float* __restrict__ ob2,
    const float* __restrict__ aw1, const float* __restrict__ ab1,
    const float* __restrict__ aw2, const float* __restrict__ ab2,
    const float* __restrict__ mw1, const float* __restrict__ mb1,
    const float* __restrict__ mw2, const float* __restrict__ mb2,
    const float* __restrict__ mw3, const float* __restrict__ mb3,
    const float* __restrict__ kw1, const float* __restrict__ kb1,
    const float* __restrict__ kw2, const float* __restrict__ kb2,
    const float* __restrict__ kw3, const float* __restrict__ kb3)
{
    extern __shared__ float sm[];
    const int tid = threadIdx.x;
    const int sbase = blockIdx.x * TS;

    // ---- obs head ----
    for (int i = tid; i < TS * OBS; i += FWD_THREADS) {
        int s = i >> 6, k = i & 63;
        sm[O_IN + s * 65 + k] = obs[(sbase + s) * OBS + k];
    }
    __syncthreads();
    layer_fwd<HID, ACT_RELU>(sm, O_T, TBS, 0, O_IN, 65, ow1, ob1, OBS);
    layer_fwd<HID, ACT_RELU>(sm, O_X, XS, 0, O_T, TBS, ow2, ob2, HID);

    // ---- action head ----
    for (int i = tid; i < TS * ACT; i += FWD_THREADS) {
        int s = i >> 4, k = i & 15;
        sm[O_IN + s * 17 + k] = action[(sbase + s) * ACT + k];
    }
    __syncthreads();
    layer_fwd<HID, ACT_RELU>(sm, O_T, TBS, 0, O_IN, 17, aw1, ab1, ACT);
    layer_fwd<HID, ACT_RELU>(sm, O_X, XS, 128, O_T, TBS, aw2, ab2, HID);

    // ---- f-net layer 1: h1 = relu(x @ mw1^T + mb1) ----
    layer_fwd<COMP, ACT_RELU>(sm, O_H1, HS, 0, O_X, XS, mw1, mb1, CON);
    if (tid < TS * 3) {
        int s = tid / 3, w = tid - 3 * s;
        unsigned m = 0;
        for (int b = 0; b < 32; b++) {
            int idx = w * 32 + b;
            if (idx < COMP && sm[O_H1 + s * HS + idx] > 0.f) m |= 1u << b;
        }
        g_d1m[(sbase + s) * 3 + w] = m;
    }
    // ---- f-net layer 2 ----
    layer_fwd<COMP, ACT_RELU>(sm, O_H2, HS, 0, O_H1, HS, mw2, mb2, COMP);
    if (tid < TS * 3) {
        int s = tid / 3, w = tid - 3 * s;
        unsigned m = 0;
        for (int b = 0; b < 32; b++) {
            int idx = w * 32 + b;
            if (idx < COMP && sm[O_H2 + s * HS + idx] > 0.f) m |= 1u << b;
        }
        g_d2m[(sbase + s) * 3 + w] = m;
    }
    // ---- f-net layer 3 -> f_out (overwrites h1 region) ----
    layer_fwd<COMP, ACT_RELU>(sm, O_H1, HS, 0, O_H2, HS, mw3, mb3, COMP);
    for (int i = tid; i < TS * COMP; i += FWD_THREADS) {
        int s = i / COMP, o = i - s * COMP;
        g_fout[(sbase + s) * COMP + o] = sm[O_H1 + s * HS + o];
    }
    // ---- k-net ----
    layer_fwd<KS, ACT_TANH>(sm, O_K1, 33, 0, O_X, XS, kw1, kb1, CON);
    layer_fwd<16, ACT_TANH>(sm, O_K2, 17, 0, O_K1, 33, kw2, kb2, KS);
    if (tid < TS) {
        float z = kb3[0];
        #pragma unroll
        for (int i = 0; i < 16; i++) z = fmaf(sm[O_K2 + tid * 17 + i], kw3[i], z);
        g_kout[sbase + tid] = (z > 20.f) ? z : log1pf(expf(z));
    }
}

// =========================================================================
// Kernel 3: Jacobian norm + final output.
//   ||J||^2 = sum_{a,b} (Bc^T Bc)[a,b] * Gc[a,b],  Bc = W3c @ W2c.
//   2x4 register tiles (95% thread utilization), Gc staged in smem
//   (overlays CW3 after GEMM1), forced 2 CTAs/SM.
// =========================================================================
#define SPC 4   // samples per CTA (sequential)

// smem layout (float offsets), stride 88
#define J_CW3  0                 // 88 x 88  (Gc overlays this after GEMM1)
#define J_CW2  7744              // 88 x 88
#define J_CB   15488             // 88 x 88
#define J_FROW 23232             // 88
#define J_A1   23320             // 88 ints
#define J_A2   23408
#define J_A3   23496
#define J_CNT  23584             // 4
#define J_WSUM 23588             // 8
#define JAC_SMEM_FLOATS 23600
#define JAC_SMEM_BYTES  (JAC_SMEM_FLOATS * 4)

__global__ __launch_bounds__(256, 2)
void jac_kernel(const float* __restrict__ mw2, const float* __restrict__ mw3,
                float* __restrict__ out)
{
    extern __shared__ float sm[];
    const int tid = threadIdx.x;
    int* act1 = (int*)(sm + J_A1);
    int* act2 = (int*)(sm + J_A2);
    int* act3 = (int*)(sm + J_A3);
    int* cnt  = (int*)(sm + J_CNT);
    float* frow = sm + J_FROW;

    for (int ss = 0; ss < SPC; ss++) {
        int gs = blockIdx.x * SPC + ss;

        if (tid < COMP) frow[tid] = g_fout[gs * COMP + tid];
        __syncthreads();

        // build compacted index lists: warp L handles level L (L=0,1,2)
        if (tid < 96) {
            int L = tid >> 5;
            int lane = tid & 31;
            int base = 0;
            int* act = (L == 0) ? act1 : ((L == 1) ? act2 : act3);
            for (int w = 0; w < 3; w++) {
                unsigned word;
                if (L == 0)      word = g_d1m[gs * 3 + w];
                else if (L == 1) word = g_d2m[gs * 3 + w];
                else {
                    int idx = w * 32 + lane;
                    int fl = (idx < COMP) && (frow[idx] > 0.f);
                    word = __ballot_sync(0xFFFFFFFFu, fl);
                }
                int idx = w * 32 + lane;
                if ((word >> lane) & 1u) {
                    int pos = base + __popc(word & ((1u << lane) - 1u));
                    act[pos] = idx;
                }
                base += __popc(word);
            }
            // zero-pad act1 so padded Gc gathers stay in-bounds
            if (L == 0) {
                int np = (base + 3) & ~3;
                for (int p = base + lane; p < np; p += 32) act[p] = 0;
            }
            if (lane == 0) cnt[L] = base;
        }
        __syncthreads();
        const int n1 = cnt[0], n2 = cnt[1], n3 = cnt[2];
        const int n1p = (n1 + 3) & ~3;
        const int n3p = (n3 + 3) & ~3;

        // gather compacted W3, W2 from global (L1-resident after sample 0)
        for (int e = tid; e < n3p * n2; e += 256) {
            int ii = e / n2, mm = e - ii * n2;
            sm[J_CW3 + ii * 88 + mm] =
                (ii < n3) ? __ldg(mw3 + act3[ii] * COMP + act2[mm]) : 0.f;
        }
        for (int e = tid; e < n2 * n1p; e += 256) {
            int mm = e / n1p, jj = e - mm * n1p;
            sm[J_CW2 + mm * 88 + jj] =
                (jj < n1) ? __ldg(mw2 + act2[mm] * COMP + act1[jj]) : 0.f;
        }
        __syncthreads();

        const int nb1 = n1p >> 2;          // 4-wide col tiles
        const int nr3 = n3p >> 1;          // 2-high row tiles

        // Bc[n3p x n1p] = W3c @ W2c  (K = n2), 2x4 register tiles
        for (int t = tid; t < nr3 * nb1; t += 256) {
            int bi = t / nb1, bj = t - bi * nb1;
            int ii = bi << 1, jj = bj << 2;
            float a00=0,a01=0,a02=0,a03=0;
            float a10=0,a11=0,a12=0,a13=0;
            const float* w3 = sm + J_CW3 + ii * 88;
            const float* w2 = sm + J_CW2 + jj;
            #pragma unroll 2
            for (int kk = 0; kk < n2; kk++) {
                float x0 = w3[kk];
                float x1 = w3[88 + kk];
                float4 b = *(const float4*)(w2 + kk * 88);
                a00 = fmaf(x0, b.x, a00); a01 = fmaf(x0, b.y, a01);
                a02 = fmaf(x0, b.z, a02); a03 = fmaf(x0, b.w, a03);
                a10 = fmaf(x1, b.x, a10); a11 = fmaf(x1, b.y, a11);
                a12 = fmaf(x1, b.z, a12); a13 = fmaf(x1, b.w, a13);
            }
            float* cb = sm + J_CB + ii * 88 + jj;
            *(float4*)(cb)      = make_float4(a00, a01, a02, a03);
            *(float4*)(cb + 88) = make_float4(a10, a11, a12, a13);
        }
        __syncthreads();

        // gather Gc into CW3's space: Gc[a,b] = G[act1[a], act1[b]]
        float* gc = sm + J_CW3;
        for (int e = tid; e < n1p * n1p; e += 256) {
            int a = e / n1p, b = e - a * n1p;
            gc[a * 88 + b] = __ldg(g_G + act1[a] * COMP + act1[b]);
        }
        __syncthreads();

        // trace = sum_{a,b} (Bc^T Bc)[a,b] * Gc[a,b]; 2x4 (a,b) tiles, K=n3
        const int nr1 = n1p >> 1;
        float local = 0.f;
        for (int t = tid; t < nr1 * nb1; t += 256) {
            int bi = t / nb1, bj = t - bi * nb1;
            int aa = bi << 1, bb = bj << 2;
            const float* ca = sm + J_CB + aa;
            const float* cbp = sm + J_CB + bb;
            float s00=0,s01=0,s02=0,s03=0;
            float s10=0,s11=0,s12=0,s13=0;
            #pragma unroll 2
            for (int kk = 0; kk < n3; kk++) {
                float u0 = ca[kk * 88];
                float u1 = ca[kk * 88 + 1];
                float4 v = *(const float4*)(cbp + kk * 88);
                s00 = fmaf(u0, v.x, s00); s01 = fmaf(u0, v.y, s01);
                s02 = fmaf(u0, v.z, s02); s03 = fmaf(u0, v.w, s03);
                s10 = fmaf(u1, v.x, s10); s11 = fmaf(u1, v.y, s11);
                s12 = fmaf(u1, v.z, s12); s13 = fmaf(u1, v.w, s13);
            }
            const float* g0 = gc + aa * 88 + bb;
            float4 q0 = *(const float4*)(g0);
            float4 q1 = *(const float4*)(g0 + 88);
            local += s00*q0.x + s01*q0.y + s02*q0.z + s03*q0.w
                   + s10*q1.x + s11*q1.y + s12*q1.z + s13*q1.w;
        }
        #pragma unroll
        for (int off = 16; off; off >>= 1)
            local += __shfl_down_sync(0xFFFFFFFFu, local, off);
        if ((tid & 31) == 0) sm[J_WSUM + (tid >> 5)] = local;
        __syncthreads();

        if (tid < COMP) {
            float ns = 0.f;
            #pragma unroll
            for (int w = 0; w < 8; w++) ns += sm[J_WSUM + w];
            float scal = 1.f / (sqrtf(ns) + 1e-4f);
            float kv = g_kout[gs];
            out[gs * COMP + tid] = tanhf(kv * frow[tid] * scal);
        }
        __syncthreads();  // protect frow/cnt/buffers reuse next sample
    }
}

// =========================================================================
// launch
// =========================================================================
extern "C" void kernel_launch(void* const* d_in, const int* in_sizes, int n_in,
                              void* d_out, int out_size)
{
    const float* obs    = (const float*)d_in[0];
    const float* action = (const float*)d_in[1];
    const float* ow1 = (const float*)d_in[2];
    const float* ob1 = (const float*)d_in[3];
    const float* ow2 = (const float*)d_in[4];
    const float* ob2 = (const float*)d_in[5];
    const float* aw1 = (const float*)d_in[6];
    const float* ab1 = (const float*)d_in[7];
    const float* aw2 = (const float*)d_in[8];
    const float* ab2 = (const float*)d_in[9];
    const float* mw1 = (const float*)d_in[10];
    const float* mb1 = (const float*)d_in[11];
    const float* mw2 = (const float*)d_in[12];
    const float* mb2 = (const float*)d_in[13];
    const float* mw3 = (const float*)d_in[14];
    const float* mb3 = (const float*)d_in[15];
    const float* kw1 = (const float*)d_in[16];
    const float* kb1 = (const float*)d_in[17];
    const float* kw2 = (const float*)d_in[18];
    const float* kb2 = (const float*)d_in[19];
    const float* kw3 = (const float*)d_in[20];
    const float* kb3 = (const float*)d_in[21];
    float* out = (float*)d_out;

    cudaFuncSetAttribute(fwd_kernel, cudaFuncAttributeMaxDynamicSharedMemorySize,
                         FWD_SMEM_BYTES);
    cudaFuncSetAttribute(jac_kernel, cudaFuncAttributeMaxDynamicSharedMemorySize,
                         JAC_SMEM_BYTES);

    g_kernel<<<(COMP * COMP * 32 + 255) / 256, 256>>>(mw1);
    fwd_kernel<<<BATCH / TS, FWD_THREADS, FWD_SMEM_BYTES>>>(
        obs, action, ow1, ob1, ow2, ob2, aw1, ab1, aw2, ab2,
        mw1, mb1, mw2, mb2, mw3, mb3, kw1, kb1, kw2, kb2, kw3, kb3);
    jac_kernel<<<BATCH / SPC, 256, JAC_SMEM_BYTES>>>(mw2, mw3, out);
}

// round 5
// speedup vs baseline: 1.2679x; 1.2679x over previous
#include <cuda_runtime.h>
#include <math.h>
#include <stdint.h>

// Problem dims
#define BATCH 8192
#define OBS 64
#define ACT 16
#define HID 128
#define CON 256
#define COMP 85
#define KS 32

// ---------------- scratch (device globals; no allocation) ----------------
__device__ float g_G[COMP * COMP];          // W1 W1^T
__device__ float g_fout[BATCH * COMP];      // f-net output (relu(p3))
__device__ float g_kout[BATCH];             // k-net output (softplus)
__device__ unsigned g_d1m[BATCH * 3];       // d1 bitmask (85 bits in 3 words)
__device__ unsigned g_d2m[BATCH * 3];       // d2 bitmask

// ---- cp.async helpers (4-byte scattered gather, fire-and-forget) ----
__device__ __forceinline__ void cpa4(uint32_t dst_smem, const float* src) {
    asm volatile("cp.async.ca.shared.global [%0], [%1], 4;"
                 :: "r"(dst_smem), "l"(src));
}
__device__ __forceinline__ void cpa_commit_wait() {
    asm volatile("cp.async.commit_group;" ::: "memory");
    asm volatile("cp.async.wait_group 0;" ::: "memory");
}

// =========================================================================
// Kernel 1: G = mw1 @ mw1^T   (85x85, K=256). One warp per output element.
// =========================================================================
__global__ __launch_bounds__(256)
void g_kernel(const float* __restrict__ mw1) {
    int gw = (blockIdx.x * 256 + threadIdx.x) >> 5;   // global warp id
    int lane = threadIdx.x & 31;
    if (gw >= COMP * COMP) return;
    int i = gw / COMP;
    int j = gw - i * COMP;
    const float4* a = (const float4*)(mw1 + i * CON);
    const float4* b = (const float4*)(mw1 + j * CON);
    float acc = 0.f;
    #pragma unroll
    for (int t = 0; t < 2; t++) {
        float4 av = a[lane + 32 * t];
        float4 bv = b[lane + 32 * t];
        acc += av.x * bv.x + av.y * bv.y + av.z * bv.z + av.w * bv.w;
    }
    #pragma unroll
    for (int off = 16; off; off >>= 1)
        acc += __shfl_down_sync(0xFFFFFFFFu, acc, off);
    if (lane == 0) g_G[gw] = acc;
}

// =========================================================================
// Kernel 2: fused forward pass. 64 samples per CTA, 512 threads.
// K is a template parameter -> staging loops fully unrolled (batched LDGs).
// =========================================================================
#define TS 64
#define FWD_THREADS 512

// smem layout (float offsets)
#define O_X   0            // x buffer 64 x 257 (concat of/af)
#define XS    257
#define O_W   16448        // weight staging 16512 floats
#define O_T   32960        // head layer-1 temp 64 x 129
#define TBS   129
#define O_IN  41216        // input staging 64 x 65 (also k1/k2 bufs)
#define O_K1  41216        // k1: 64 x 33
#define O_K2  43328        // k2: 64 x 17
#define O_H1  45376        // h1 / f_out: 64 x 87
#define O_H2  50944        // h2: 64 x 87
#define HS    87
#define FWD_SMEM_FLOATS 56512
#define FWD_SMEM_BYTES  (FWD_SMEM_FLOATS * 4)

#define ACT_RELU 0
#define ACT_TANH 1

template<int N, int K, int ACTT>
__device__ __forceinline__ void layer_fwd(
    float* __restrict__ sm,
    int o_out, int outStride, int outColOff,
    int o_in, int inStride,
    const float* __restrict__ Wg, const float* __restrict__ bg)
{
    constexpr int NJ = (N + 31) / 32;
    const int tid = threadIdx.x;
    const int sp = tid >> 5;       // 0..15, samples 4sp..4sp+3
    const int q = tid & 31;        // output col group

    float acc[4][NJ];
    #pragma unroll
    for (int s = 0; s < 4; s++)
        #pragma unroll
        for (int j = 0; j < NJ; j++) acc[s][j] = 0.f;

    float* wbuf = sm + O_W;
    constexpr int KC = (K > 128) ? 128 : K;
    constexpr int WS = KC | 1;     // odd stride -> conflict-free weight columns

    #pragma unroll
    for (int k0 = 0; k0 < K; k0 += KC) {
        __syncthreads();
        // staging: compile-time trip count -> unrolled, batched LDGs
        {
            constexpr int TOT = N * KC;
            constexpr int NIT = (TOT + FWD_THREADS - 1) / FWD_THREADS;
            int i = tid;
            #pragma unroll
            for (int u = 0; u < NIT; u++) {
                if (i < TOT) {
                    int r = i / KC;
                    int c = i - r * KC;
                    wbuf[r * WS + c] = Wg[r * K + k0 + c];
                }
                i += FWD_THREADS;
            }
        }
        __syncthreads();
        const float* in0 = sm + o_in + (4 * sp + 0) * inStride + k0;
        const float* in1 = sm + o_in + (4 * sp + 1) * inStride + k0;
        const float* in2 = sm + o_in + (4 * sp + 2) * inStride + k0;
        const float* in3 = sm + o_in + (4 * sp + 3) * inStride + k0;
        #pragma unroll 2
        for (int k = 0; k < KC; k++) {
            float a0 = in0[k], a1 = in1[k], a2 = in2[k], a3 = in3[k];
            const float* wr = wbuf + k + q * WS;
            #pragma unroll
            for (int j = 0; j < NJ; j++) {
                float w = wr[(j << 5) * WS];
                acc[0][j] = fmaf(a0, w, acc[0][j]);
                acc[1][j] = fmaf(a1, w, acc[1][j]);
                acc[2][j] = fmaf(a2, w, acc[2][j]);
                acc[3][j] = fmaf(a3, w, acc[3][j]);
            }
        }
    }
    #pragma unroll
    for (int j = 0; j < NJ; j++) {
        int o = q + (j << 5);
        if (o < N) {
            float bv = bg[o];
            #pragma unroll
            for (int s = 0; s < 4; s++) {
                float v = acc[s][j] + bv;
                if (ACTT == ACT_RELU) v = fmaxf(v, 0.f);
                else if (ACTT == ACT_TANH) v = tanhf(v);
                sm[o_out + (4 * sp + s) * outStride + outColOff + o] = v;
            }
        }
    }
    __syncthreads();
}

__global__ __launch_bounds__(FWD_THREADS)
void fwd_kernel(
    const float* __restrict__ obs, const float* __restrict__ action,
    const float* __restrict__ ow1, const float* __restrict__ ob1,
    const float* __restrict__ ow2, const float* __restrict__ ob2,
    const float* __restrict__ aw1, const float* __restrict__ ab1,
    const float* __restrict__ aw2, const float* __restrict__ ab2,
    const float* __restrict__ mw1, const float* __restrict__ mb1,
    const float* __restrict__ mw2, const float* __restrict__ mb2,
    const float* __restrict__ mw3, const float* __restrict__ mb3,
    const float* __restrict__ kw1, const float* __restrict__ kb1,
    const float* __restrict__ kw2, const float* __restrict__ kb2,
    const float* __restrict__ kw3, const float* __restrict__ kb3)
{
    extern __shared__ float sm[];
    const int tid = threadIdx.x;
    const int sbase = blockIdx.x * TS;

    // ---- obs head ----
    for (int i = tid; i < TS * OBS; i += FWD_THREADS) {
        int s = i >> 6, k = i & 63;
        sm[O_IN + s * 65 + k] = obs[(sbase + s) * OBS + k];
    }
    __syncthreads();
    layer_fwd<HID, OBS, ACT_RELU>(sm, O_T, TBS, 0, O_IN, 65, ow1, ob1);
    layer_fwd<HID, HID, ACT_RELU>(sm, O_X, XS, 0, O_T, TBS, ow2, ob2);

    // ---- action head ----
    for (int i = tid; i < TS * ACT; i += FWD_THREADS) {
        int s = i >> 4, k = i & 15;
        sm[O_IN + s * 17 + k] = action[(sbase + s) * ACT + k];
    }
    __syncthreads();
    layer_fwd<HID, ACT, ACT_RELU>(sm, O_T, TBS, 0, O_IN, 17, aw1, ab1);
    layer_fwd<HID, HID, ACT_RELU>(sm, O_X, XS, 128, O_T, TBS, aw2, ab2);

    // ---- f-net layer 1: h1 = relu(x @ mw1^T + mb1) ----
    layer_fwd<COMP, CON, ACT_RELU>(sm, O_H1, HS, 0, O_X, XS, mw1, mb1);
    if (tid < TS * 3) {
        int s = tid / 3, w = tid - 3 * s;
        unsigned m = 0;
        for (int b = 0; b < 32; b++) {
            int idx = w * 32 + b;
            if (idx < COMP && sm[O_H1 + s * HS + idx] > 0.f) m |= 1u << b;
        }
        g_d1m[(sbase + s) * 3 + w] = m;
    }
    // ---- f-net layer 2 ----
    layer_fwd<COMP, COMP, ACT_RELU>(sm, O_H2, HS, 0, O_H1, HS, mw2, mb2);
    if (tid < TS * 3) {
        int s = tid / 3, w = tid - 3 * s;
        unsigned m = 0;
        for (int b = 0; b < 32; b++) {
            int idx = w * 32 + b;
            if (idx < COMP && sm[O_H2 + s * HS + idx] > 0.f) m |= 1u << b;
        }
        g_d2m[(sbase + s) * 3 + w] = m;
    }
    // ---- f-net layer 3 -> f_out (overwrites h1 region) ----
    layer_fwd<COMP, COMP, ACT_RELU>(sm, O_H1, HS, 0, O_H2, HS, mw3, mb3);
    for (int i = tid; i < TS * COMP; i += FWD_THREADS) {
        int s = i / COMP, o = i - s * COMP;
        g_fout[(sbase + s) * COMP + o] = sm[O_H1 + s * HS + o];
    }
    // ---- k-net ----
    layer_fwd<KS, CON, ACT_TANH>(sm, O_K1, 33, 0, O_X, XS, kw1, kb1);
    layer_fwd<16, KS, ACT_TANH>(sm, O_K2, 17, 0, O_K1, 33, kw2, kb2);
    if (tid < TS) {
        float z = kb3[0];
        #pragma unroll
        for (int i = 0; i < 16; i++) z = fmaf(sm[O_K2 + tid * 17 + i], kw3[i], z);
        g_kout[sbase + tid] = (z > 20.f) ? z : log1pf(expf(z));
    }
}

// =========================================================================
// Kernel 3: Jacobian norm + final output.
//   ||J||^2 = sum_{a,b} (Bc^T Bc)[a,b] * Gc[a,b],  Bc = W3c @ W2c.
//   cp.async gathers (full MLP), hoisted per-CTA setup, 4x4 tiles,
//   symmetric trace (bi<=bj only), 2 CTAs/SM.
// =========================================================================
#define SPC 4   // samples per CTA (sequential)

// smem layout (float offsets), stride 88
#define J_CW3   0                // 88 x 88  (Gc overlays this after GEMM1)
#define J_CW2   7744             // 88 x 88
#define J_CB    15488            // 88 x 88
#define J_FROWS 23232            // SPC x 88
#define J_KOUT  23584            // SPC
#define J_MASKS 23588            // 24 unsigned (SPC x 3 d1, SPC x 3 d2)
#define J_ACTL  23612            // SPC*3*88 ints (act lists)
#define J_CNT   24668            // SPC*3 ints
#define J_WSUM  24680            // 8
#define JAC_SMEM_FLOATS 24688
#define JAC_SMEM_BYTES  (JAC_SMEM_FLOATS * 4)

__global__ __launch_bounds__(256, 2)
void jac_kernel(const float* __restrict__ mw2, const float* __restrict__ mw3,
                float* __restrict__ out)
{
    extern __shared__ float sm[];
    const int tid = threadIdx.x;
    const int wid = tid >> 5;
    const int lane = tid & 31;
    const int gs0 = blockIdx.x * SPC;
    unsigned* um = (unsigned*)(sm + J_MASKS);
    int* actl = (int*)(sm + J_ACTL);
    int* cnt = (int*)(sm + J_CNT);
    const uint32_t sb = (uint32_t)__cvta_generic_to_shared(sm);

    // ---- Phase A: hoisted per-CTA setup ----
    for (int i = tid; i < SPC * COMP; i += 256) {
        int s = i / COMP, c = i - s * COMP;
        sm[J_FROWS + s * 88 + c] = g_fout[(gs0 + s) * COMP + c];
    }
    if (tid < SPC) sm[J_KOUT + tid] = g_kout[gs0 + tid];
    if (tid >= 32 && tid < 32 + SPC * 3) um[tid - 32] = g_d1m[gs0 * 3 + tid - 32];
    if (tid >= 64 && tid < 64 + SPC * 3) um[SPC * 3 + tid - 64] = g_d2m[gs0 * 3 + tid - 64];
    __syncthreads();

    // build all SPC*3 act lists, one warp-task each
    for (int task = wid; task < SPC * 3; task += 8) {
        int s = task / 3, L = task - 3 * s;
        int* act = actl + task * 88;
        int base = 0;
        for (int w = 0; w < 3; w++) {
            unsigned word;
            if (L == 0)      word = um[s * 3 + w];
            else if (L == 1) word = um[SPC * 3 + s * 3 + w];
            else {
                int idx = w * 32 + lane;
                word = __ballot_sync(0xFFFFFFFFu,
                                     idx < COMP && sm[J_FROWS + s * 88 + idx] > 0.f);
            }
            int idx = w * 32 + lane;
            if ((word >> lane) & 1u)
                act[base + __popc(word & ((1u << lane) - 1u))] = idx;
            base += __popc(word);
        }
        if (L == 0) {   // zero-pad act1 so Gc gathers stay in-bounds
            int np = (base + 3) & ~3;
            for (int p = base + lane; p < np; p += 32) act[p] = 0;
        }
        if (lane == 0) cnt[task] = base;
    }
    __syncthreads();

    // ---- per-sample loop ----
    for (int ss = 0; ss < SPC; ss++) {
        const int* act1 = actl + (ss * 3 + 0) * 88;
        const int* act2 = actl + (ss * 3 + 1) * 88;
        const int* act3 = actl + (ss * 3 + 2) * 88;
        const int n1 = cnt[ss * 3], n2 = cnt[ss * 3 + 1], n3 = cnt[ss * 3 + 2];
        const int n1p = (n1 + 3) & ~3;
        const int n3p = (n3 + 3) & ~3;
        const int nb1 = n1p >> 2, nb3 = n3p >> 2;

        // gather W3c rows + W2c rows via cp.async (full MLP, no reg roundtrip)
        for (int r = wid; r < n3; r += 8) {
            const float* src = mw3 + act3[r] * COMP;
            uint32_t drow = sb + (J_CW3 + r * 88) * 4;
            for (int c = lane; c < n2; c += 32) cpa4(drow + c * 4, src + act2[c]);
        }
        for (int r = wid; r < n2; r += 8) {
            const float* src = mw2 + act2[r] * COMP;
            uint32_t drow = sb + (J_CW2 + r * 88) * 4;
            for (int c = lane; c < n1p; c += 32) {
                if (c < n1) cpa4(drow + c * 4, src + act1[c]);
                else sm[J_CW2 + r * 88 + c] = 0.f;   // pad cols must be exact 0
            }
        }
        cpa_commit_wait();
        __syncthreads();

        // Bc[n3p x n1p] = W3c @ W2c  (K = n2), 4x4 register tiles.
        // Rows >= n3 read stale smem (finite garbage); their CB rows are
        // never read by the trace (k-loop bounded by n3).
        for (int t = tid; t < nb3 * nb1; t += 256) {
            int bi = t / nb1, bj = t - bi * nb1;
            int ii = bi << 2, jj = bj << 2;
            float a00=0,a01=0,a02=0,a03=0, a10=0,a11=0,a12=0,a13=0;
            float a20=0,a21=0,a22=0,a23=0, a30=0,a31=0,a32=0,a33=0;
            const float* w3 = sm + J_CW3 + ii * 88;
            const float* w2 = sm + J_CW2 + jj;
            #pragma unroll 2
            for (int kk = 0; kk < n2; kk++) {
                float x0 = w3[kk];
                float x1 = w3[88 + kk];
                float x2 = w3[176 + kk];
                float x3 = w3[264 + kk];
                float4 b = *(const float4*)(w2 + kk * 88);
                a00 = fmaf(x0, b.x, a00); a01 = fmaf(x0, b.y, a01);
                a02 = fmaf(x0, b.z, a02); a03 = fmaf(x0, b.w, a03);
                a10 = fmaf(x1, b.x, a10); a11 = fmaf(x1, b.y, a11);
                a12 = fmaf(x1, b.z, a12); a13 = fmaf(x1, b.w, a13);
                a20 = fmaf(x2, b.x, a20); a21 = fmaf(x2, b.y, a21);
                a22 = fmaf(x2, b.z, a22); a23 = fmaf(x2, b.w, a23);
                a30 = fmaf(x3, b.x, a30); a31 = fmaf(x3, b.y, a31);
                a32 = fmaf(x3, b.z, a32); a33 = fmaf(x3, b.w, a33);
            }
            float* cb = sm + J_CB + ii * 88 + jj;
            *(float4*)(cb)       = make_float4(a00, a01, a02, a03);
            *(float4*)(cb + 88)  = make_float4(a10, a11, a12, a13);
            *(float4*)(cb + 176) = make_float4(a20, a21, a22, a23);
            *(float4*)(cb + 264) = make_float4(a30, a31, a32, a33);
        }
        __syncthreads();

        // gather Gc into CW3's space (act1 zero-padded -> always in-bounds)
        float* gc = sm + J_CW3;
        for (int r = wid; r < n1p; r += 8) {
            const float* src = g_G + act1[r] * COMP;
            uint32_t drow = sb + (J_CW3 + r * 88) * 4;
            for (int c = lane; c < n1p; c += 32) cpa4(drow + c * 4, src + act1[c]);
        }
        cpa_commit_wait();
        __syncthreads();

        // trace = sum_{a,b} (Bc^T Bc)[a,b] * Gc[a,b]; symmetric: bi<=bj tiles,
        // off-diagonal doubled. K = n3 (exact).
        float local = 0.f;
        for (int t = tid; t < nb1 * nb1; t += 256) {
            int bi = t / nb1, bj = t - bi * nb1;
            if (bi > bj) continue;
            int aa = bi << 2, bb = bj << 2;
            const float* ca = sm + J_CB + aa;
            const float* cbp = sm + J_CB + bb;
            float s00=0,s01=0,s02=0,s03=0, s10=0,s11=0,s12=0,s13=0;
            float s20=0,s21=0,s22=0,s23=0, s30=0,s31=0,s32=0,s33=0;
            #pragma unroll 2
            for (int kk = 0; kk < n3; kk++) {
                float4 u = *(const float4*)(ca + kk * 88);
                float4 v = *(const float4*)(cbp + kk * 88);
                s00 = fmaf(u.x, v.x, s00); s01 = fmaf(u.x, v.y, s01);
                s02 = fmaf(u.x, v.z, s02); s03 = fmaf(u.x, v.w, s03);
                s10 = fmaf(u.y, v.x, s10); s11 = fmaf(u.y, v.y, s11);
                s12 = fmaf(u.y, v.z, s12); s13 = fmaf(u.y, v.w, s13);
                s20 = fmaf(u.z, v.x, s20); s21 = fmaf(u.z, v.y, s21);
                s22 = fmaf(u.z, v.z, s22); s23 = fmaf(u.z, v.w, s23);
                s30 = fmaf(u.w, v.x, s30); s31 = fmaf(u.w, v.y, s31);
                s32 = fmaf(u.w, v.z, s32); s33 = fmaf(u.w, v.w, s33);
            }
            const float* g0 = gc + aa * 88 + bb;
            float4 q0 = *(const float4*)(g0);
            float4 q1 = *(const float4*)(g0 + 88);
            float4 q2 = *(const float4*)(g0 + 176);
            float4 q3 = *(const float4*)(g0 + 264);
            float part =
                  s00*q0.x + s01*q0.y + s02*q0.z + s03*q0.w
                + s10*q1.x + s11*q1.y + s12*q1.z + s13*q1.w
                + s20*q2.x + s21*q2.y + s22*q2.z + s23*q2.w
                + s30*q3.x + s31*q3.y + s32*q3.z + s33*q3.w;
            local += (bi < bj) ? 2.f * part : part;
        }
        #pragma unroll
        for (int off = 16; off; off >>= 1)
            local += __shfl_down_sync(0xFFFFFFFFu, local, off);
        if (lane == 0) sm[J_WSUM + wid] = local;
        __syncthreads();

        if (tid < COMP) {
            float ns = 0.f;
            #pragma unroll
            for (int w = 0; w < 8; w++) ns += sm[J_WSUM + w];
            float scal = 1.f / (sqrtf(ns) + 1e-4f);
            float kv = sm[J_KOUT + ss];
            out[(gs0 + ss) * COMP + tid] = tanhf(kv * sm[J_FROWS + ss * 88 + tid] * scal);
        }
        __syncthreads();
    }
}

// =========================================================================
// launch
// =========================================================================
extern "C" void kernel_launch(void* const* d_in, const int* in_sizes, int n_in,
                              void* d_out, int out_size)
{
    const float* obs    = (const float*)d_in[0];
    const float* action = (const float*)d_in[1];
    const float* ow1 = (const float*)d_in[2];
    const float* ob1 = (const float*)d_in[3];
    const float* ow2 = (const float*)d_in[4];
    const float* ob2 = (const float*)d_in[5];
    const float* aw1 = (const float*)d_in[6];
    const float* ab1 = (const float*)d_in[7];
    const float* aw2 = (const float*)d_in[8];
    const float* ab2 = (const float*)d_in[9];
    const float* mw1 = (const float*)d_in[10];
    const float* mb1 = (const float*)d_in[11];
    const float* mw2 = (const float*)d_in[12];
    const float* mb2 = (const float*)d_in[13];
    const float* mw3 = (const float*)d_in[14];
    const float* mb3 = (const float*)d_in[15];
    const float* kw1 = (const float*)d_in[16];
    const float* kb1 = (const float*)d_in[17];
    const float* kw2 = (const float*)d_in[18];
    const float* kb2 = (const float*)d_in[19];
    const float* kw3 = (const float*)d_in[20];
    const float* kb3 = (const float*)d_in[21];
    float* out = (float*)d_out;

    cudaFuncSetAttribute(fwd_kernel, cudaFuncAttributeMaxDynamicSharedMemorySize,
                         FWD_SMEM_BYTES);
    cudaFuncSetAttribute(jac_kernel, cudaFuncAttributeMaxDynamicSharedMemorySize,
                         JAC_SMEM_BYTES);

    g_kernel<<<(COMP * COMP * 32 + 255) / 256, 256>>>(mw1);
    fwd_kernel<<<BATCH / TS, FWD_THREADS, FWD_SMEM_BYTES>>>(
        obs, action, ow1, ob1, ow2, ob2, aw1, ab1, aw2, ab2,
        mw1, mb1, mw2, mb2, mw3, mb3, kw1, kb1, kw2, kb2, kw3, kb3);
    jac_kernel<<<BATCH / SPC, 256, JAC_SMEM_BYTES>>>(mw2, mw3, out);
}